// round 7
// baseline (speedup 1.0000x reference)
#include <cuda_runtime.h>
#include <cuda_bf16.h>
#include <cstdint>

#define N_TOK   2048
#define BATCH   64
#define SDIM    512
#define EDIM    512
#define NSPLIT  8
#define CHUNK   (N_TOK / NSPLIT)      // 256
#define RPW     (CHUNK / 4)           // 64 rows per warp
#define RPI     2                     // rows per iteration
#define NIT     (RPW / RPI)           // 32
#define THREADS 128

// Scratch: partial softmax stats + weighted accumulators per (split, b).
__device__ float  g_m[NSPLIT * BATCH];
__device__ float  g_l[NSPLIT * BATCH];
__device__ float4 g_acc4[NSPLIT * BATCH * (EDIM / 4)];   // 1 MiB
__device__ int    g_cnt[BATCH];                          // zero-init; reset after merge

// ---------------------------------------------------------------------------
// grid = (NSPLIT, BATCH), block = 128 (4 warps).
// Each WARP owns complete rows: lane covers float4 columns {lane+32j}.
// Dot reduces via warp shfl only -> NO barrier in the mainloop; warps
// free-run so memory stalls de-align across the CTA.
// ---------------------------------------------------------------------------
__global__ void __launch_bounds__(THREADS)
attn_fused(const float* __restrict__ emb, const float* __restrict__ W,
           float* __restrict__ out)
{
    const int split = blockIdx.x;
    const int b     = blockIdx.y;
    const int t     = threadIdx.x;
    const int warp  = t >> 5;
    const int lane  = t & 31;

    __shared__ float4 sh_acc4[4][EDIM / 4];   // 8 KB
    __shared__ float  sh_m[4], sh_l[4];
    __shared__ int    sh_last;

    // W_e slice for this lane's 4 col4 positions.
    const float4* W4 = reinterpret_cast<const float4*>(W + SDIM);
    float4 we[4];
    #pragma unroll
    for (int j = 0; j < 4; j++) we[j] = W4[lane + 32 * j];

    float4 acc[4];
    #pragma unroll
    for (int j = 0; j < 4; j++) acc[j] = make_float4(0.f, 0.f, 0.f, 0.f);
    float m = -1e30f, l = 0.f;

    const int row0 = split * CHUNK + warp * RPW;
    // emb[n,b,e]: float4 base for (b, lane), row stride = B*ED/4 = 8192
    const float4* base = reinterpret_cast<const float4*>(emb)
                       + (size_t)b * (EDIM / 4) + lane;
    const size_t nstride = (size_t)BATCH * (EDIM / 4);

    // --- prologue: load rows row0, row0+1 ---
    float4 vbuf[2][RPI][4];
    #pragma unroll
    for (int r = 0; r < RPI; r++)
        #pragma unroll
        for (int j = 0; j < 4; j++)
            vbuf[0][r][j] = __ldcs(base + (size_t)(row0 + r) * nstride + 32 * j);

    for (int it = 0; it < NIT; it++) {
        const int cur = it & 1;
        const int nxt = cur ^ 1;

        // prefetch next 2 rows (8 LDG.128 in flight through the reduce)
        if (it + 1 < NIT) {
            const float4* p = base + (size_t)(row0 + (it + 1) * RPI) * nstride;
            #pragma unroll
            for (int r = 0; r < RPI; r++)
                #pragma unroll
                for (int j = 0; j < 4; j++)
                    vbuf[nxt][r][j] = __ldcs(p + (size_t)r * nstride + 32 * j);
        }

        // per-lane partial dots (2 independent chains each to shorten latency)
        float pd[RPI];
        #pragma unroll
        for (int r = 0; r < RPI; r++) {
            float a0 = 0.f, a1 = 0.f;
            #pragma unroll
            for (int j = 0; j < 4; j++) {
                const float4 v = vbuf[cur][r][j];
                a0 += v.x * we[j].x + v.y * we[j].y;
                a1 += v.z * we[j].z + v.w * we[j].w;
            }
            pd[r] = a0 + a1;
        }

        // warp butterfly reduce: every lane gets the full dot
        #pragma unroll
        for (int off = 16; off; off >>= 1)
            #pragma unroll
            for (int r = 0; r < RPI; r++)
                pd[r] += __shfl_xor_sync(0xffffffffu, pd[r], off);

        // online softmax update (warp-local, all lanes identical stats)
        const float m_new = fmaxf(m, fmaxf(pd[0], pd[1]));
        const float scale = __expf(m - m_new);
        const float p0 = __expf(pd[0] - m_new);
        const float p1 = __expf(pd[1] - m_new);
        m = m_new;
        l = l * scale + p0 + p1;
        #pragma unroll
        for (int j = 0; j < 4; j++) {
            acc[j].x = acc[j].x * scale + p0 * vbuf[cur][0][j].x + p1 * vbuf[cur][1][j].x;
            acc[j].y = acc[j].y * scale + p0 * vbuf[cur][0][j].y + p1 * vbuf[cur][1][j].y;
            acc[j].z = acc[j].z * scale + p0 * vbuf[cur][0][j].z + p1 * vbuf[cur][1][j].z;
            acc[j].w = acc[j].w * scale + p0 * vbuf[cur][0][j].w + p1 * vbuf[cur][1][j].w;
        }
    }

    // --- intra-CTA merge of the 4 warps (first barriers of the kernel) ---
    if (lane == 0) { sh_m[warp] = m; sh_l[warp] = l; }
    __syncthreads();
    const float M  = fmaxf(fmaxf(sh_m[0], sh_m[1]), fmaxf(sh_m[2], sh_m[3]));
    const float ws = __expf(m - M);            // this warp's rescale
    const float Lt = sh_l[0] * __expf(sh_m[0] - M) + sh_l[1] * __expf(sh_m[1] - M)
                   + sh_l[2] * __expf(sh_m[2] - M) + sh_l[3] * __expf(sh_m[3] - M);
    #pragma unroll
    for (int j = 0; j < 4; j++)
        sh_acc4[warp][lane + 32 * j] =
            make_float4(acc[j].x * ws, acc[j].y * ws, acc[j].z * ws, acc[j].w * ws);
    __syncthreads();

    float4 o = sh_acc4[0][t];
    #pragma unroll
    for (int w = 1; w < 4; w++) {
        const float4 a = sh_acc4[w][t];
        o.x += a.x; o.y += a.y; o.z += a.z; o.w += a.w;
    }

    // --- publish partials ---
    const int sb = split * BATCH + b;
    if (t == 0) { g_m[sb] = M; g_l[sb] = Lt; }
    g_acc4[(size_t)sb * (EDIM / 4) + t] = o;

    // --- last CTA per b merges all splits ---
    __threadfence();
    if (t == 0) {
        int old = atomicAdd(&g_cnt[b], 1);
        sh_last = (old == NSPLIT - 1);
    }
    __syncthreads();
    if (!sh_last) return;
    __threadfence();

    float MM = -1e30f;
    #pragma unroll
    for (int s = 0; s < NSPLIT; s++)
        MM = fmaxf(MM, g_m[s * BATCH + b]);

    float wgt[NSPLIT];
    float L = 0.f;
    #pragma unroll
    for (int s = 0; s < NSPLIT; s++) {
        wgt[s] = __expf(g_m[s * BATCH + b] - MM);
        L     += wgt[s] * g_l[s * BATCH + b];
    }
    const float inv = 1.0f / L;

    float4 oo = make_float4(0.f, 0.f, 0.f, 0.f);
    #pragma unroll
    for (int s = 0; s < NSPLIT; s++) {
        const float4 a = g_acc4[(size_t)(s * BATCH + b) * (EDIM / 4) + t];
        oo.x += wgt[s] * a.x;
        oo.y += wgt[s] * a.y;
        oo.z += wgt[s] * a.z;
        oo.w += wgt[s] * a.w;
    }
    oo.x *= inv; oo.y *= inv; oo.z *= inv; oo.w *= inv;
    reinterpret_cast<float4*>(out)[(size_t)b * (EDIM / 4) + t] = oo;

    if (t == 0) g_cnt[b] = 0;   // reset for next replay
}

// ---------------------------------------------------------------------------
// Inputs (metadata order): 0=state_tm1 (B,SD)  1=embeddings (N,B,ED)
//                          2=W (SD+ED,1)       3=b (1,)
// state_tm1 / b / W_s cancel in the softmax over n. Output: (B, ED) f32.
// ---------------------------------------------------------------------------
extern "C" void kernel_launch(void* const* d_in, const int* in_sizes, int n_in,
                              void* d_out, int out_size)
{
    const float* emb = (const float*)d_in[1];
    const float* W   = (const float*)d_in[2];
    float*       out = (float*)d_out;

    dim3 grid(NSPLIT, BATCH);
    attn_fused<<<grid, THREADS>>>(emb, W, out);
}

// round 10
// speedup vs baseline: 1.5265x; 1.5265x over previous
#include <cuda_runtime.h>
#include <cuda_bf16.h>
#include <cstdint>

#define N_TOK   2048
#define BATCH   64
#define SDIM    512
#define EDIM    512
#define NSPLIT  16
#define CHUNK   (N_TOK / NSPLIT)   // 128
#define NT      8                  // rows per tile
#define NTILES  (CHUNK / NT)       // 16
#define THREADS 128                // each thread owns one float4 of E

// Scratch: partial softmax stats + weighted accumulators per (split, b).
__device__ float g_m[NSPLIT * BATCH];
__device__ float g_l[NSPLIT * BATCH];
__device__ float g_acc[NSPLIT * BATCH * EDIM];   // 2 MiB
__device__ int   g_cnt[BATCH];                   // zero-init; reset after merge

// ---------------------------------------------------------------------------
// Single fused kernel. grid = (NSPLIT, BATCH), block = 128.
// Per CTA: online-softmax over its 128-row chunk (embeddings read exactly
// once, streaming), then the LAST CTA per batch column merges all splits.
// Structure identical to the measured-good R3 kernel; only NSPLIT changed.
// ---------------------------------------------------------------------------
__global__ void __launch_bounds__(THREADS)
attn_fused(const float* __restrict__ emb, const float* __restrict__ W,
           float* __restrict__ out)
{
    const int split = blockIdx.x;
    const int b     = blockIdx.y;
    const int t     = threadIdx.x;          // 0..127
    const int warp  = t >> 5;
    const int lane  = t & 31;

    __shared__ float sh_red[2][4][NT];      // double-buffered cross-warp partials
    __shared__ int   sh_last;

    // W_e slice for this thread's 4 E-dims (W is (SD+ED,1) contiguous).
    const float4 we = reinterpret_cast<const float4*>(W + SDIM)[t];

    float4 acc = make_float4(0.f, 0.f, 0.f, 0.f);
    float  m   = -1e30f;
    float  l   = 0.f;

    const int n0 = split * CHUNK;
    // emb[n,b,e] at n*B*ED + b*ED + e ; float4 stride per n = B*ED/4 = 8192
    const float4* e4 = reinterpret_cast<const float4*>(emb)
                     + (size_t)n0 * (BATCH * (EDIM / 4))
                     + (size_t)b * (EDIM / 4) + t;
    const size_t n_stride = (size_t)BATCH * (EDIM / 4);

    // --- prologue: load tile 0 ---
    float4 vbuf[2][NT];
    #pragma unroll
    for (int i = 0; i < NT; i++)
        vbuf[0][i] = __ldcs(e4 + (size_t)i * n_stride);

    #pragma unroll 2
    for (int it = 0; it < NTILES; it++) {
        const int cur = it & 1;
        const int nxt = cur ^ 1;

        // partial dots for current tile
        float pd[NT];
        #pragma unroll
        for (int i = 0; i < NT; i++)
            pd[i] = vbuf[cur][i].x * we.x + vbuf[cur][i].y * we.y
                  + vbuf[cur][i].z * we.z + vbuf[cur][i].w * we.w;

        // prefetch next tile — keeps LDGs in flight through the reduction
        if (it + 1 < NTILES) {
            const float4* p = e4 + (size_t)(it + 1) * NT * n_stride;
            #pragma unroll
            for (int i = 0; i < NT; i++)
                vbuf[nxt][i] = __ldcs(p + (size_t)i * n_stride);
        }

        // warp reduce all NT dots
        #pragma unroll
        for (int off = 16; off; off >>= 1) {
            #pragma unroll
            for (int i = 0; i < NT; i++)
                pd[i] += __shfl_xor_sync(0xffffffffu, pd[i], off);
        }
        if (lane == 0) {
            #pragma unroll
            for (int i = 0; i < NT; i++)
                sh_red[cur][warp][i] = pd[i];
        }
        __syncthreads();                     // ONLY barrier this tile

        // every thread finalizes logits + softmax update redundantly
        float lg[NT];
        #pragma unroll
        for (int i = 0; i < NT; i++)
            lg[i] = sh_red[cur][0][i] + sh_red[cur][1][i]
                  + sh_red[cur][2][i] + sh_red[cur][3][i];

        float tm = lg[0];
        #pragma unroll
        for (int i = 1; i < NT; i++) tm = fmaxf(tm, lg[i]);
        const float m_new = fmaxf(m, tm);
        const float scale = __expf(m - m_new);
        m = m_new;
        l *= scale;
        acc.x *= scale; acc.y *= scale; acc.z *= scale; acc.w *= scale;
        #pragma unroll
        for (int i = 0; i < NT; i++) {
            const float p = __expf(lg[i] - m_new);
            l     += p;
            acc.x += p * vbuf[cur][i].x;
            acc.y += p * vbuf[cur][i].y;
            acc.z += p * vbuf[cur][i].z;
            acc.w += p * vbuf[cur][i].w;
        }
    }

    // --- publish partials ---
    const int sb = split * BATCH + b;
    if (t == 0) { g_m[sb] = m; g_l[sb] = l; }
    reinterpret_cast<float4*>(g_acc)[(size_t)sb * (EDIM / 4) + t] = acc;

    // --- last CTA per b merges all splits (fused pass2) ---
    __threadfence();
    if (t == 0) {
        int old = atomicAdd(&g_cnt[b], 1);
        sh_last = (old == NSPLIT - 1);
    }
    __syncthreads();
    if (!sh_last) return;
    __threadfence();   // order partial reads after observing the final count

    float M = -1e30f;
    #pragma unroll
    for (int s = 0; s < NSPLIT; s++)
        M = fmaxf(M, g_m[s * BATCH + b]);

    float w[NSPLIT];
    float L = 0.f;
    #pragma unroll
    for (int s = 0; s < NSPLIT; s++) {
        w[s] = __expf(g_m[s * BATCH + b] - M);
        L   += w[s] * g_l[s * BATCH + b];
    }
    const float inv = 1.0f / L;

    float4 o = make_float4(0.f, 0.f, 0.f, 0.f);
    #pragma unroll
    for (int s = 0; s < NSPLIT; s++) {
        const float4 a = reinterpret_cast<const float4*>(g_acc)
                             [(size_t)(s * BATCH + b) * (EDIM / 4) + t];
        o.x += w[s] * a.x;
        o.y += w[s] * a.y;
        o.z += w[s] * a.z;
        o.w += w[s] * a.w;
    }
    o.x *= inv; o.y *= inv; o.z *= inv; o.w *= inv;
    reinterpret_cast<float4*>(out)[(size_t)b * (EDIM / 4) + t] = o;

    if (t == 0) g_cnt[b] = 0;   // reset for next replay (graph-deterministic)
}

// ---------------------------------------------------------------------------
// Inputs (metadata order): 0=state_tm1 (B,SD)  1=embeddings (N,B,ED)
//                          2=W (SD+ED,1)       3=b (1,)
// state_tm1 / b / W_s cancel in the softmax over n. Output: (B, ED) f32.
// ---------------------------------------------------------------------------
extern "C" void kernel_launch(void* const* d_in, const int* in_sizes, int n_in,
                              void* d_out, int out_size)
{
    const float* emb = (const float*)d_in[1];
    const float* W   = (const float*)d_in[2];
    float*       out = (float*)d_out;

    dim3 grid(NSPLIT, BATCH);
    attn_fused<<<grid, THREADS>>>(emb, W, out);
}